// round 16
// baseline (speedup 1.0000x reference)
#include <cuda_runtime.h>
#include <cuda_fp16.h>
#include <cstdint>

typedef unsigned long long ull;

#define BB 512
#define TT 1024
#define IDIM 15
#define HH 64
#define ODIM 11
#define CHUNK 64
#define NCHUNK (TT/CHUNK)
#define XCH_FLOATS 960
#define XCH_UNITS  240
#define XBUF_FLOATS 976

// scratch (static __device__ — no allocations in kernel_launch)
__device__ __align__(16) __half2 g_hs[(size_t)BB*TT*32];   // hidden states, fp16 pairs

// ---- f32x2 helpers ----
__device__ __forceinline__ ull ffma2(ull a, ull b, ull c){
    ull d; asm("fma.rn.f32x2 %0, %1, %2, %3;" : "=l"(d) : "l"(a), "l"(b), "l"(c)); return d;
}
__device__ __forceinline__ ull fadd2(ull a, ull b){
    ull d; asm("add.rn.f32x2 %0, %1, %2;" : "=l"(d) : "l"(a), "l"(b)); return d;
}
__device__ __forceinline__ ull pack2(float x, float y){
    ull r; asm("mov.b64 %0, {%1, %2};" : "=l"(r) : "f"(x), "f"(y)); return r;
}
__device__ __forceinline__ float2 unpack2(ull v){
    float2 r; asm("mov.b64 {%0, %1}, %2;" : "=f"(r.x), "=f"(r.y) : "l"(v)); return r;
}

// ---- single fused kernel: xproj(raw x) + recurrence, then per-block decoder ----
__global__ void __launch_bounds__(128,1) rnn_dec_kernel(
    const float* __restrict__ x,
    const float* __restrict__ W_ih, const float* __restrict__ b_ih,
    const float* __restrict__ W_hh, const float* __restrict__ b_hh,
    const float* __restrict__ W_dec, const float* __restrict__ b_dec,
    float* __restrict__ out, float* __restrict__ h_out)
{
    __shared__ __align__(16) float xs[2][4][XBUF_FLOATS];   // raw x chunks (+guards)
    __shared__ __align__(16) ull  h_sh[4][2][32];           // per-warp h exchange
    __shared__ __align__(16) float wd_f[ODIM*HH];           // dec weights (fp32)
    __shared__ float bd[ODIM];
    __shared__ __align__(16) float outsh[4][32*ODIM];       // dec staging

    const int tid = threadIdx.x;
    const int wid = tid >> 5;
    const int l   = tid & 31;
    const int b   = blockIdx.x * 4 + wid;
    const int j0 = 2*l, j1 = 2*l + 1;

    // stage decoder weights once (used in the epilogue)
    for (int i = tid; i < ODIM*HH; i += 128) wd_f[i] = W_dec[i];
    if (tid < ODIM) bd[tid] = b_dec[tid];

    // W_hh rows j0,j1 in registers, k-paired as f32x2
    ull w0[32], w1[32];
    {
        const ull* wp = (const ull*)W_hh;
        #pragma unroll
        for (int q=0;q<32;q++){ w0[q] = wp[j0*32+q]; w1[q] = wp[j1*32+q]; }
    }
    // W_ih rows with parity-specific pairing (raw 60B-stride x rows):
    ull wE0[8], wE1[8], wO0[8], wO1[8];
    {
        float r0[IDIM], r1[IDIM];
        #pragma unroll
        for (int i=0;i<IDIM;i++){ r0[i] = W_ih[j0*IDIM+i]; r1[i] = W_ih[j1*IDIM+i]; }
        #pragma unroll
        for (int q=0;q<7;q++){
            wE0[q] = pack2(r0[2*q],   r0[2*q+1]);
            wE1[q] = pack2(r1[2*q],   r1[2*q+1]);
            wO0[q+1] = pack2(r0[2*q+1], r0[2*q+2]);
            wO1[q+1] = pack2(r1[2*q+1], r1[2*q+2]);
        }
        wE0[7] = pack2(r0[14], 0.f);  wE1[7] = pack2(r1[14], 0.f);
        wO0[0] = pack2(0.f, r0[0]);   wO1[0] = pack2(0.f, r1[0]);
    }
    const ull bias0 = pack2(b_ih[j0]+b_hh[j0], 0.f);
    const ull bias1 = pack2(b_ih[j1]+b_hh[j1], 0.f);

    h_sh[wid][1][l] = 0ULL;   // h_{-1} = 0 (t=0 reads slot 1)

    const uint32_t xs_base0 = (uint32_t)__cvta_generic_to_shared(&xs[0][wid][4]);
    const float* xsrc = x + (size_t)b * (TT*IDIM);

    auto prefetch = [&](int c){
        if (c < NCHUNK){
            const float* src = xsrc + (size_t)c * XCH_FLOATS;
            uint32_t dst = xs_base0 + (uint32_t)(c & 1) * (uint32_t)sizeof(xs[0]);
            #pragma unroll
            for (int q=0;q<8;q++){
                int idx = q*32 + l;
                if (idx < XCH_UNITS){
                    asm volatile("cp.async.ca.shared.global [%0], [%1], 16;\n"
                        :: "r"(dst + (uint32_t)(idx*16)), "l"(src + idx*4) : "memory");
                }
            }
        }
        asm volatile("cp.async.commit_group;\n" ::: "memory");
    };

    prefetch(0);

    __half2* hs_ptr = g_hs + (size_t)b * (TT*32) + l;
    ull hlast = 0ULL;

    // ======================= phase 1: recurrence =======================
    for (int c=0; c<NCHUNK; c++){
        prefetch(c+1);
        asm volatile("cp.async.wait_group 1;\n" ::: "memory");
        __syncwarp();
        const float* xbuf = &xs[c & 1][wid][0];

        #pragma unroll 4
        for (int tt=0; tt<CHUNK; tt++){
            const int rs = (tt & 1) ^ 1;
            const int ws =  tt & 1;
            ull ax0 = bias0, ax1 = bias1;
            if ((tt & 1) == 0){
                const ull* xv = (const ull*)(xbuf + 4 + 15*tt);
                #pragma unroll
                for (int q=0;q<8;q++){
                    ull xq = xv[q];
                    ax0 = ffma2(xq, wE0[q], ax0);
                    ax1 = ffma2(xq, wE1[q], ax1);
                }
            } else {
                const ull* xv = (const ull*)(xbuf + 3 + 15*tt);
                #pragma unroll
                for (int q=0;q<8;q++){
                    ull xq = xv[q];
                    ax0 = ffma2(xq, wO0[q], ax0);
                    ax1 = ffma2(xq, wO1[q], ax1);
                }
            }
            const ulonglong2* hp = (const ulonglong2*)&h_sh[wid][rs][0];
            ull aa0=ax0, aa1=ax1, ab0=0ULL, ab1=0ULL;
            #pragma unroll
            for (int q=0;q<16;q++){
                ulonglong2 hv = hp[q];
                aa0 = ffma2(hv.x, w0[2*q],   aa0);
                aa1 = ffma2(hv.x, w1[2*q],   aa1);
                ab0 = ffma2(hv.y, w0[2*q+1], ab0);
                ab1 = ffma2(hv.y, w1[2*q+1], ab1);
            }
            float2 s0 = unpack2(fadd2(aa0, ab0));
            float2 s1 = unpack2(fadd2(aa1, ab1));
            float h0v = fmaxf(s0.x + s0.y, 0.f);
            float h1v = fmaxf(s1.x + s1.y, 0.f);
            ull hpk = pack2(h0v, h1v);
            h_sh[wid][ws][l] = hpk;
            *hs_ptr = __floats2half2_rn(h0v, h1v);
            hs_ptr += 32;
            hlast = hpk;
            asm volatile("" ::: "memory");
        }
    }
    ((ull*)h_out)[b*32 + l] = hlast;

    // ======================= phase 2: decoder ==========================
    // make this warp's hs STGs visible to all its lanes' LDGs
    __threadfence_block();
    __syncwarp();

    const ull* wd2 = (const ull*)wd_f;
    float* outp = out + (size_t)b * (TT*ODIM);

    for (int it=0; it<TT/32; it++){
        const int t = it*32 + l;                      // this lane's row
        // load own row: 64 halfs = 128B (one L1 line; 8 LDG.128)
        const uint4* src = (const uint4*)(g_hs + ((size_t)b*TT + t)*32);
        ull row[32];
        #pragma unroll
        for (int q=0;q<8;q++){
            uint4 v = src[q];
            const __half2* hv = (const __half2*)&v;
            #pragma unroll
            for (int k=0;k<4;k++){
                float2 f = __half22float2(hv[k]);
                row[q*4+k] = pack2(f.x, f.y);
            }
        }
        // 11 dots from registers; wd via broadcast LDS
        #pragma unroll
        for (int o=0;o<ODIM;o++){
            ull a0=0ULL, a1=0ULL, a2=0ULL, a3=0ULL;
            #pragma unroll
            for (int kk=0;kk<32;kk+=4){
                a0 = ffma2(row[kk],   wd2[o*32+kk],   a0);
                a1 = ffma2(row[kk+1], wd2[o*32+kk+1], a1);
                a2 = ffma2(row[kk+2], wd2[o*32+kk+2], a2);
                a3 = ffma2(row[kk+3], wd2[o*32+kk+3], a3);
            }
            float2 s = unpack2(fadd2(fadd2(a0,a1), fadd2(a2,a3)));
            outsh[wid][l*ODIM + o] = fmaxf(s.x + s.y + bd[o], 0.f);
        }
        __syncwarp();
        // coalesced store: 32 rows x 11 floats = 88 float4
        float4* dst = (float4*)(outp + (size_t)it * (32*ODIM));
        const float4* osrc = (const float4*)&outsh[wid][0];
        #pragma unroll
        for (int q=0;q<3;q++){
            int idx = q*32 + l;
            if (idx < 88) dst[idx] = osrc[idx];
        }
        __syncwarp();
    }
}

extern "C" void kernel_launch(void* const* d_in, const int* in_sizes, int n_in,
                              void* d_out, int out_size)
{
    const float* x     = (const float*)d_in[0];
    const float* W_ih  = (const float*)d_in[1];
    const float* b_ih  = (const float*)d_in[2];
    const float* W_hh  = (const float*)d_in[3];
    const float* b_hh  = (const float*)d_in[4];
    const float* W_dec = (const float*)d_in[5];
    const float* b_dec = (const float*)d_in[6];
    float* out = (float*)d_out;

    (void)in_sizes; (void)n_in; (void)out_size;

    rnn_dec_kernel<<<BB/4, 128>>>(x, W_ih, b_ih, W_hh, b_hh, W_dec, b_dec,
                                  out, out + (size_t)BB*TT*ODIM);
}

// round 17
// speedup vs baseline: 1.0907x; 1.0907x over previous
#include <cuda_runtime.h>
#include <cuda_fp16.h>
#include <cstdint>

typedef unsigned long long ull;

#define BB 512
#define TT 1024
#define IDIM 15
#define HH 64
#define ODIM 11
#define CHUNK 64
#define NCHUNK (TT/CHUNK)
#define XCH_FLOATS 960
#define XCH_UNITS  240
#define XBUF_FLOATS 976

// scratch (static __device__ — no allocations in kernel_launch)
__device__ __align__(16) __half2 g_hs[(size_t)BB*TT*32];   // hidden states, fp16 pairs

// ---- f32x2 helpers ----
__device__ __forceinline__ ull ffma2(ull a, ull b, ull c){
    ull d; asm("fma.rn.f32x2 %0, %1, %2, %3;" : "=l"(d) : "l"(a), "l"(b), "l"(c)); return d;
}
__device__ __forceinline__ ull fadd2(ull a, ull b){
    ull d; asm("add.rn.f32x2 %0, %1, %2;" : "=l"(d) : "l"(a), "l"(b)); return d;
}
__device__ __forceinline__ ull pack2(float x, float y){
    ull r; asm("mov.b64 %0, {%1, %2};" : "=l"(r) : "f"(x), "f"(y)); return r;
}
__device__ __forceinline__ float2 unpack2(ull v){
    float2 r; asm("mov.b64 {%0, %1}, %2;" : "=f"(r.x), "=f"(r.y) : "l"(v)); return r;
}

// ---- kernel 1: fused xproj(raw x) + recurrence. warp == one batch row ----
__global__ void __launch_bounds__(128,1) rnn_kernel(
    const float* __restrict__ x,
    const float* __restrict__ W_ih, const float* __restrict__ b_ih,
    const float* __restrict__ W_hh, const float* __restrict__ b_hh,
    float* __restrict__ h_out)
{
    __shared__ __align__(16) float xs[2][4][XBUF_FLOATS];
    __shared__ __align__(16) ull  h_sh[4][2][32];

    const int wid = threadIdx.x >> 5;
    const int l   = threadIdx.x & 31;
    const int b   = blockIdx.x * 4 + wid;
    const int j0 = 2*l, j1 = 2*l + 1;

    ull w0[32], w1[32];
    {
        const ull* wp = (const ull*)W_hh;
        #pragma unroll
        for (int q=0;q<32;q++){ w0[q] = wp[j0*32+q]; w1[q] = wp[j1*32+q]; }
    }
    // W_ih rows with parity-specific pairing (raw 60B-stride x rows)
    ull wE0[8], wE1[8], wO0[8], wO1[8];
    {
        float r0[IDIM], r1[IDIM];
        #pragma unroll
        for (int i=0;i<IDIM;i++){ r0[i] = W_ih[j0*IDIM+i]; r1[i] = W_ih[j1*IDIM+i]; }
        #pragma unroll
        for (int q=0;q<7;q++){
            wE0[q] = pack2(r0[2*q],   r0[2*q+1]);
            wE1[q] = pack2(r1[2*q],   r1[2*q+1]);
            wO0[q+1] = pack2(r0[2*q+1], r0[2*q+2]);
            wO1[q+1] = pack2(r1[2*q+1], r1[2*q+2]);
        }
        wE0[7] = pack2(r0[14], 0.f);  wE1[7] = pack2(r1[14], 0.f);
        wO0[0] = pack2(0.f, r0[0]);   wO1[0] = pack2(0.f, r1[0]);
    }
    const ull bias0 = pack2(b_ih[j0]+b_hh[j0], 0.f);
    const ull bias1 = pack2(b_ih[j1]+b_hh[j1], 0.f);

    h_sh[wid][1][l] = 0ULL;

    const uint32_t xs_base0 = (uint32_t)__cvta_generic_to_shared(&xs[0][wid][4]);
    const float* xsrc = x + (size_t)b * (TT*IDIM);

    auto prefetch = [&](int c){
        if (c < NCHUNK){
            const float* src = xsrc + (size_t)c * XCH_FLOATS;
            uint32_t dst = xs_base0 + (uint32_t)(c & 1) * (uint32_t)sizeof(xs[0]);
            #pragma unroll
            for (int q=0;q<8;q++){
                int idx = q*32 + l;
                if (idx < XCH_UNITS){
                    asm volatile("cp.async.ca.shared.global [%0], [%1], 16;\n"
                        :: "r"(dst + (uint32_t)(idx*16)), "l"(src + idx*4) : "memory");
                }
            }
        }
        asm volatile("cp.async.commit_group;\n" ::: "memory");
    };

    prefetch(0);

    __half2* hs_ptr = g_hs + (size_t)b * (TT*32) + l;
    ull hlast = 0ULL;

    for (int c=0; c<NCHUNK; c++){
        prefetch(c+1);
        asm volatile("cp.async.wait_group 1;\n" ::: "memory");
        __syncwarp();
        const float* xbuf = &xs[c & 1][wid][0];

        #pragma unroll 4
        for (int tt=0; tt<CHUNK; tt++){
            const int rs = (tt & 1) ^ 1;
            const int ws =  tt & 1;
            ull ax0 = bias0, ax1 = bias1;
            if ((tt & 1) == 0){
                const ull* xv = (const ull*)(xbuf + 4 + 15*tt);
                #pragma unroll
                for (int q=0;q<8;q++){
                    ull xq = xv[q];
                    ax0 = ffma2(xq, wE0[q], ax0);
                    ax1 = ffma2(xq, wE1[q], ax1);
                }
            } else {
                const ull* xv = (const ull*)(xbuf + 3 + 15*tt);
                #pragma unroll
                for (int q=0;q<8;q++){
                    ull xq = xv[q];
                    ax0 = ffma2(xq, wO0[q], ax0);
                    ax1 = ffma2(xq, wO1[q], ax1);
                }
            }
            const ulonglong2* hp = (const ulonglong2*)&h_sh[wid][rs][0];
            ull aa0=ax0, aa1=ax1, ab0=0ULL, ab1=0ULL;
            #pragma unroll
            for (int q=0;q<16;q++){
                ulonglong2 hv = hp[q];
                aa0 = ffma2(hv.x, w0[2*q],   aa0);
                aa1 = ffma2(hv.x, w1[2*q],   aa1);
                ab0 = ffma2(hv.y, w0[2*q+1], ab0);
                ab1 = ffma2(hv.y, w1[2*q+1], ab1);
            }
            float2 s0 = unpack2(fadd2(aa0, ab0));
            float2 s1 = unpack2(fadd2(aa1, ab1));
            float h0v = fmaxf(s0.x + s0.y, 0.f);
            float h1v = fmaxf(s1.x + s1.y, 0.f);
            ull hpk = pack2(h0v, h1v);
            h_sh[wid][ws][l] = hpk;
            *hs_ptr = __floats2half2_rn(h0v, h1v);
            hs_ptr += 32;
            hlast = hpk;
            asm volatile("" ::: "memory");
        }
    }
    ((ull*)h_out)[b*32 + l] = hlast;
}

// ---- kernel 2: decoder. Coalesced staging -> register-resident row -> 11 dots ----
__global__ void __launch_bounds__(128) dec_kernel(
    const float* __restrict__ W_dec, const float* __restrict__ b_dec,
    float* __restrict__ out)
{
    __shared__ __align__(16) float wd_f[ODIM*HH];
    __shared__ float bd[ODIM];
    __shared__ __align__(16) ull  rows[4][32*33];       // fp32 pairs, stride 33 (2-way max)
    __shared__ __align__(16) float outsh[4][32*ODIM];

    for (int i = threadIdx.x; i < ODIM*HH; i += 128) wd_f[i] = W_dec[i];
    if (threadIdx.x < ODIM) bd[threadIdx.x] = b_dec[threadIdx.x];
    __syncthreads();

    const int wid = threadIdx.x >> 5;
    const int l   = threadIdx.x & 31;
    const int ngroups = (BB*TT)/32;   // 16384 groups of 32 rows

    for (int g = blockIdx.x*4 + wid; g < ngroups; g += gridDim.x*4){
        // coalesced load of 32 rows x 64 halfs (4KB); convert to fp32 while staging
        const uint4* src = (const uint4*)(g_hs + (size_t)g * (32*32));
        #pragma unroll
        for (int q=0;q<8;q++){
            int idx = q*32 + l;             // 0..255 (16B = 8 halfs each)
            uint4 v = src[idx];
            int row = idx >> 3;
            int cu  = (idx & 7) * 4;
            const __half2* hv = (const __half2*)&v;
            #pragma unroll
            for (int k=0;k<4;k++){
                float2 f = __half22float2(hv[k]);
                rows[wid][row*33 + cu + k] = pack2(f.x, f.y);
            }
        }
        __syncwarp();
        // hoist this lane's row into registers ONCE (32 LDS.64)
        ull row[32];
        {
            const ull* hr = &rows[wid][l*33];
            #pragma unroll
            for (int k=0;k<32;k++) row[k] = hr[k];
        }
        const ull* wd2 = (const ull*)wd_f;
        #pragma unroll
        for (int o=0;o<ODIM;o++){
            ull a0=0ULL, a1=0ULL, a2=0ULL, a3=0ULL;
            #pragma unroll
            for (int kk=0;kk<32;kk+=4){
                a0 = ffma2(row[kk],   wd2[o*32+kk],   a0);
                a1 = ffma2(row[kk+1], wd2[o*32+kk+1], a1);
                a2 = ffma2(row[kk+2], wd2[o*32+kk+2], a2);
                a3 = ffma2(row[kk+3], wd2[o*32+kk+3], a3);
            }
            float2 s = unpack2(fadd2(fadd2(a0,a1), fadd2(a2,a3)));
            outsh[wid][l*ODIM + o] = fmaxf(s.x + s.y + bd[o], 0.f);
        }
        __syncwarp();
        // coalesced store: 32*11 = 352 floats = 88 float4
        float4* dst = (float4*)(out + (size_t)g * (32*ODIM));
        const float4* osrc = (const float4*)&outsh[wid][0];
        #pragma unroll
        for (int q=0;q<3;q++){
            int idx = q*32 + l;
            if (idx < 88) dst[idx] = osrc[idx];
        }
        __syncwarp();
    }
}

extern "C" void kernel_launch(void* const* d_in, const int* in_sizes, int n_in,
                              void* d_out, int out_size)
{
    const float* x     = (const float*)d_in[0];
    const float* W_ih  = (const float*)d_in[1];
    const float* b_ih  = (const float*)d_in[2];
    const float* W_hh  = (const float*)d_in[3];
    const float* b_hh  = (const float*)d_in[4];
    const float* W_dec = (const float*)d_in[5];
    const float* b_dec = (const float*)d_in[6];
    float* out = (float*)d_out;

    (void)in_sizes; (void)n_in; (void)out_size;

    rnn_kernel<<<BB/4, 128>>>(x, W_ih, b_ih, W_hh, b_hh, out + (size_t)BB*TT*ODIM);
    dec_kernel<<<2048, 128>>>(W_dec, b_dec, out);
}